// round 1
// baseline (speedup 1.0000x reference)
#include <cuda_runtime.h>
#include <cstdint>

#define NPTS   131072
#define NBATCH 64
#define MAXPB  2560
#define MAXTOK 128
#define TOKDIM 768

// ---------------- scratch (device globals; no allocations allowed) ----------------
static __device__ float g_h96[(size_t)NPTS * 96];
static __device__ float g_a1 [(size_t)NPTS * 256];
static __device__ float g_a2 [(size_t)NPTS * 512];
static __device__ float g_a3 [(size_t)NPTS * 768];
static __device__ float g_pf [(size_t)NPTS * 768];
static __device__ float g_scores[NPTS];
static __device__ int   g_offsets[NBATCH + 1];
static __device__ int   g_selidx[NBATCH * MAXTOK];

// ---------------- per-batch offsets via binary search (batch_ids sorted) ----------
__global__ void offsets_kernel(const int* __restrict__ bids)
{
    int b = threadIdx.x;
    if (b > NBATCH) return;
    int lo = 0, hi = NPTS;
    while (lo < hi) {
        int mid = (lo + hi) >> 1;
        if (bids[mid] < b) lo = mid + 1; else hi = mid;
    }
    g_offsets[b] = lo;
}

// ---------------- pointwise: LN + spatial MLP + concat -> g_h96 -------------------
__global__ void __launch_bounds__(128)
pointwise_kernel(const float* __restrict__ coords, const float* __restrict__ feats,
                 const float* __restrict__ times,
                 const float* __restrict__ ln_g, const float* __restrict__ ln_b,
                 const float* __restrict__ sw1, const float* __restrict__ sb1,
                 const float* __restrict__ sw2, const float* __restrict__ sb2)
{
    __shared__ float s_w1[4 * 64];
    __shared__ float s_w2[64 * 64];
    __shared__ float s_b1[64], s_b2[64], s_g[4], s_bn[4];
    for (int i = threadIdx.x; i < 256; i += blockDim.x) s_w1[i] = sw1[i];
    for (int i = threadIdx.x; i < 4096; i += blockDim.x) s_w2[i] = sw2[i];
    if (threadIdx.x < 64) { s_b1[threadIdx.x] = sb1[threadIdx.x]; s_b2[threadIdx.x] = sb2[threadIdx.x]; }
    if (threadIdx.x < 4)  { s_g[threadIdx.x] = ln_g[threadIdx.x]; s_bn[threadIdx.x] = ln_b[threadIdx.x]; }
    __syncthreads();

    int i = blockIdx.x * blockDim.x + threadIdx.x;
    if (i >= NPTS) return;

    float x[4];
    x[0] = coords[3 * i + 0];
    x[1] = coords[3 * i + 1];
    x[2] = coords[3 * i + 2];
    x[3] = times[i];
    float mu = 0.25f * (x[0] + x[1] + x[2] + x[3]);
    float var = 0.f;
#pragma unroll
    for (int j = 0; j < 4; j++) { float d = x[j] - mu; var += d * d; }
    var *= 0.25f;
    float inv = rsqrtf(var + 1e-5f);
    float xn[4];
#pragma unroll
    for (int j = 0; j < 4; j++) xn[j] = (x[j] - mu) * inv * s_g[j] + s_bn[j];

    float t1[64];
#pragma unroll 8
    for (int j = 0; j < 64; j++) {
        float a = s_b1[j];
        a += xn[0] * s_w1[j];
        a += xn[1] * s_w1[64 + j];
        a += xn[2] * s_w1[128 + j];
        a += xn[3] * s_w1[192 + j];
        t1[j] = fmaxf(a, 0.f);
    }

    float* out = &g_h96[(size_t)i * 96];
#pragma unroll 8
    for (int j = 0; j < 32; j++) out[j] = feats[32 * i + j];

    for (int j = 0; j < 64; j++) {
        float a = s_b2[j];
#pragma unroll 16
        for (int k = 0; k < 64; k++) a += t1[k] * s_w2[k * 64 + j];
        out[32 + j] = fmaxf(a, 0.f);
    }
}

// ---------------- generic fp32 GEMM, 128x128x16, double-buffered ------------------
// mode 0: C = (relu?)(A@W + bias)
// mode 1: scoresOut[row] += sum_n relu(A@W + bias)[row,n] * w2[n]   (atomic partials)
__global__ void __launch_bounds__(256)
gemm_kernel(const float* __restrict__ A, const float* __restrict__ W,
            const float* __restrict__ bias, float* __restrict__ C,
            int K, int N, int do_relu,
            const float* __restrict__ w2, float* __restrict__ scoresOut, int mode)
{
    __shared__ float As[2][16][128];
    __shared__ float Bs[2][16][128];
    const int m0 = blockIdx.y * 128;
    const int n0 = blockIdx.x * 128;
    const int tid = threadIdx.x;
    const int tx = tid & 15;
    const int ty = tid >> 4;
    const int arow = tid >> 2;
    const int acol = (tid & 3) << 2;
    const int brow = tid >> 5;
    const int bcol = (tid & 31) << 2;

    const float* ag0 = A + (size_t)(m0 + arow) * K + acol;
    const float* ag1 = ag0 + (size_t)64 * K;
    const float* wg0 = W + (size_t)brow * N + n0 + bcol;
    const float* wg1 = wg0 + (size_t)8 * N;

    float acc[8][8];
#pragma unroll
    for (int i = 0; i < 8; i++)
#pragma unroll
        for (int j = 0; j < 8; j++) acc[i][j] = 0.f;

    const int nk = K >> 4;

    // prologue: tile 0 into buffer 0
    {
        float4 va0 = *(const float4*)(ag0);
        float4 va1 = *(const float4*)(ag1);
        float4 vb0 = *(const float4*)(wg0);
        float4 vb1 = *(const float4*)(wg1);
        As[0][acol + 0][arow] = va0.x; As[0][acol + 1][arow] = va0.y;
        As[0][acol + 2][arow] = va0.z; As[0][acol + 3][arow] = va0.w;
        As[0][acol + 0][arow + 64] = va1.x; As[0][acol + 1][arow + 64] = va1.y;
        As[0][acol + 2][arow + 64] = va1.z; As[0][acol + 3][arow + 64] = va1.w;
        *(float4*)&Bs[0][brow][bcol] = vb0;
        *(float4*)&Bs[0][brow + 8][bcol] = vb1;
    }
    __syncthreads();

    for (int kt = 0; kt < nk; kt++) {
        const int buf = kt & 1;
        float4 va0, va1, vb0, vb1;
        const bool more = (kt + 1 < nk);
        if (more) {
            va0 = *(const float4*)(ag0 + (kt + 1) * 16);
            va1 = *(const float4*)(ag1 + (kt + 1) * 16);
            const float* w0 = W + (size_t)((kt + 1) * 16 + brow) * N + n0 + bcol;
            vb0 = *(const float4*)(w0);
            vb1 = *(const float4*)(w0 + (size_t)8 * N);
        }
#pragma unroll
        for (int kk = 0; kk < 16; kk++) {
            float4 a0 = *(const float4*)&As[buf][kk][ty * 8];
            float4 a1 = *(const float4*)&As[buf][kk][ty * 8 + 4];
            float4 b0 = *(const float4*)&Bs[buf][kk][tx * 8];
            float4 b1 = *(const float4*)&Bs[buf][kk][tx * 8 + 4];
            float ar[8] = {a0.x, a0.y, a0.z, a0.w, a1.x, a1.y, a1.z, a1.w};
            float br[8] = {b0.x, b0.y, b0.z, b0.w, b1.x, b1.y, b1.z, b1.w};
#pragma unroll
            for (int i = 0; i < 8; i++)
#pragma unroll
                for (int j = 0; j < 8; j++)
                    acc[i][j] = fmaf(ar[i], br[j], acc[i][j]);
        }
        if (more) {
            const int nb = buf ^ 1;
            As[nb][acol + 0][arow] = va0.x; As[nb][acol + 1][arow] = va0.y;
            As[nb][acol + 2][arow] = va0.z; As[nb][acol + 3][arow] = va0.w;
            As[nb][acol + 0][arow + 64] = va1.x; As[nb][acol + 1][arow + 64] = va1.y;
            As[nb][acol + 2][arow + 64] = va1.z; As[nb][acol + 3][arow + 64] = va1.w;
            *(float4*)&Bs[nb][brow][bcol] = vb0;
            *(float4*)&Bs[nb][brow + 8][bcol] = vb1;
        }
        __syncthreads();
    }

    if (mode == 0) {
        float bia[8];
#pragma unroll
        for (int j = 0; j < 8; j++) bia[j] = bias[n0 + tx * 8 + j];
#pragma unroll
        for (int i = 0; i < 8; i++) {
            int gr = m0 + ty * 8 + i;
            float v[8];
#pragma unroll
            for (int j = 0; j < 8; j++) {
                v[j] = acc[i][j] + bia[j];
                if (do_relu) v[j] = fmaxf(v[j], 0.f);
            }
            float4* crow = (float4*)(C + (size_t)gr * N + n0 + tx * 8);
            crow[0] = make_float4(v[0], v[1], v[2], v[3]);
            crow[1] = make_float4(v[4], v[5], v[6], v[7]);
        }
    } else {
        float bia[8], w2v[8];
#pragma unroll
        for (int j = 0; j < 8; j++) {
            bia[j] = bias[n0 + tx * 8 + j];
            w2v[j] = w2[n0 + tx * 8 + j];
        }
#pragma unroll
        for (int i = 0; i < 8; i++) {
            float s = 0.f;
#pragma unroll
            for (int j = 0; j < 8; j++) {
                float v = fmaxf(acc[i][j] + bia[j], 0.f);
                s = fmaf(v, w2v[j], s);
            }
#pragma unroll
            for (int o = 8; o >= 1; o >>= 1)
                s += __shfl_xor_sync(0xffffffffu, s, o);
            if (tx == 0) atomicAdd(&scoresOut[m0 + ty * 8 + i], s);
        }
    }
}

// ---------------- init scores to hb2 -----------------------------------------------
__global__ void init_scores_kernel(const float* __restrict__ hb2)
{
    int i = blockIdx.x * blockDim.x + threadIdx.x;
    if (i < NPTS) g_scores[i] = hb2[0];
}

// ---------------- per-batch exact top-128 (tie-break: smaller position) -----------
__global__ void __launch_bounds__(256)
select_kernel()
{
    __shared__ unsigned long long keys[MAXPB];
    __shared__ unsigned long long red[8];
    const int b = blockIdx.x;
    const int off = g_offsets[b];
    int cnt = g_offsets[b + 1] - off;
    if (cnt > MAXPB) cnt = MAXPB;

    for (int p = threadIdx.x; p < cnt; p += 256) {
        float s = g_scores[off + p];
        unsigned u = __float_as_uint(s);
        u = (u & 0x80000000u) ? ~u : (u | 0x80000000u);
        keys[p] = ((unsigned long long)u << 32) | (unsigned)(0x7FFFFFFFu - p);
    }
    __syncthreads();

    const int nsel = (cnt < MAXTOK) ? cnt : MAXTOK;
    for (int t = 0; t < nsel; t++) {
        unsigned long long best = 0ull;
        for (int p = threadIdx.x; p < cnt; p += 256) {
            unsigned long long k = keys[p];
            if (k > best) best = k;
        }
#pragma unroll
        for (int o = 16; o >= 1; o >>= 1) {
            unsigned long long other = __shfl_xor_sync(0xffffffffu, best, o);
            if (other > best) best = other;
        }
        if ((threadIdx.x & 31) == 0) red[threadIdx.x >> 5] = best;
        __syncthreads();
        if (threadIdx.x == 0) {
            unsigned long long m = red[0];
#pragma unroll
            for (int w = 1; w < 8; w++) if (red[w] > m) m = red[w];
            int pos = 0x7FFFFFFF - (int)(unsigned)(m & 0xFFFFFFFFull);
            keys[pos] = 0ull;
            g_selidx[b * MAXTOK + t] = off + pos;
        }
        __syncthreads();
    }
    if (threadIdx.x == 0)
        for (int t = nsel; t < MAXTOK; t++) g_selidx[b * MAXTOK + t] = -1;
}

// ---------------- gather tokens / centroids / mask into d_out ---------------------
__global__ void __launch_bounds__(192)
gather_kernel(const float* __restrict__ coords, const float* __restrict__ times,
              float* __restrict__ out)
{
    const int slot = blockIdx.x;                 // b*128 + t
    const int idx = g_selidx[slot];
    float4* d4 = (float4*)(out + (size_t)slot * TOKDIM);
    if (idx >= 0) {
        const float4* s4 = (const float4*)&g_pf[(size_t)idx * TOKDIM];
        for (int j = threadIdx.x; j < TOKDIM / 4; j += blockDim.x) d4[j] = s4[j];
    } else {
        float4 z = make_float4(0.f, 0.f, 0.f, 0.f);
        for (int j = threadIdx.x; j < TOKDIM / 4; j += blockDim.x) d4[j] = z;
    }
    if (threadIdx.x == 0) {
        float* cen = out + (size_t)NBATCH * MAXTOK * TOKDIM + (size_t)slot * 4;
        float* msk = out + (size_t)NBATCH * MAXTOK * TOKDIM + (size_t)NBATCH * MAXTOK * 4 + slot;
        if (idx >= 0) {
            cen[0] = coords[3 * idx + 0];
            cen[1] = coords[3 * idx + 1];
            cen[2] = coords[3 * idx + 2];
            cen[3] = times[idx];
            *msk = 1.0f;
        } else {
            cen[0] = 0.f; cen[1] = 0.f; cen[2] = 0.f; cen[3] = 0.f;
            *msk = 0.0f;
        }
    }
}

// ---------------- launch ------------------------------------------------------------
extern "C" void kernel_launch(void* const* d_in, const int* in_sizes, int n_in,
                              void* d_out, int out_size)
{
    const float* coords = (const float*)d_in[0];
    const float* feats  = (const float*)d_in[1];
    const float* times  = (const float*)d_in[2];
    const int*   bids   = (const int*)  d_in[3];
    const float* ln_g = (const float*)d_in[4];
    const float* ln_b = (const float*)d_in[5];
    const float* sw1  = (const float*)d_in[6];
    const float* sb1  = (const float*)d_in[7];
    const float* sw2  = (const float*)d_in[8];
    const float* sb2  = (const float*)d_in[9];
    const float* mw1  = (const float*)d_in[10];
    const float* mb1  = (const float*)d_in[11];
    const float* mw2  = (const float*)d_in[12];
    const float* mb2  = (const float*)d_in[13];
    const float* mw3  = (const float*)d_in[14];
    const float* mb3  = (const float*)d_in[15];
    const float* mw4  = (const float*)d_in[16];
    const float* mb4  = (const float*)d_in[17];
    const float* hw1  = (const float*)d_in[18];
    const float* hb1  = (const float*)d_in[19];
    const float* hw2  = (const float*)d_in[20];
    const float* hb2  = (const float*)d_in[21];
    float* out = (float*)d_out;

    // device-global scratch addresses (query only; no allocation)
    void *p_h96, *p_a1, *p_a2, *p_a3, *p_pf, *p_scores;
    cudaGetSymbolAddress(&p_h96, g_h96);
    cudaGetSymbolAddress(&p_a1, g_a1);
    cudaGetSymbolAddress(&p_a2, g_a2);
    cudaGetSymbolAddress(&p_a3, g_a3);
    cudaGetSymbolAddress(&p_pf, g_pf);
    cudaGetSymbolAddress(&p_scores, g_scores);
    float* h96 = (float*)p_h96;
    float* a1 = (float*)p_a1;
    float* a2 = (float*)p_a2;
    float* a3 = (float*)p_a3;
    float* pf = (float*)p_pf;
    float* scores = (float*)p_scores;

    offsets_kernel<<<1, NBATCH + 1>>>(bids);
    pointwise_kernel<<<NPTS / 128, 128>>>(coords, feats, times, ln_g, ln_b, sw1, sb1, sw2, sb2);

    // MLP chain
    gemm_kernel<<<dim3(256 / 128, NPTS / 128), 256>>>(h96, mw1, mb1, a1, 96, 256, 1, nullptr, nullptr, 0);
    gemm_kernel<<<dim3(512 / 128, NPTS / 128), 256>>>(a1, mw2, mb2, a2, 256, 512, 1, nullptr, nullptr, 0);
    gemm_kernel<<<dim3(768 / 128, NPTS / 128), 256>>>(a2, mw3, mb3, a3, 512, 768, 1, nullptr, nullptr, 0);
    gemm_kernel<<<dim3(768 / 128, NPTS / 128), 256>>>(a3, mw4, mb4, pf, 768, 768, 0, nullptr, nullptr, 0);

    // fused score head: relu(pf@hw1+hb1)@hw2 + hb2
    init_scores_kernel<<<NPTS / 256, 256>>>(hb2);
    gemm_kernel<<<dim3(384 / 128, NPTS / 128), 256>>>(pf, hw1, hb1, nullptr, 768, 384, 1, hw2, scores, 1);

    // per-batch top-128 + gather
    select_kernel<<<NBATCH, 256>>>();
    gather_kernel<<<NBATCH * MAXTOK, 192>>>(coords, times, out);
}

// round 2
// speedup vs baseline: 1.0004x; 1.0004x over previous
#include <cuda_runtime.h>
#include <cstdint>

#define NPTS   131072
#define NBATCH 64
#define MAXPB  2560
#define MAXTOK 128
#define TOKDIM 768

// ---------------- scratch (device globals; no allocations allowed) ----------------
static __device__ float g_h96[(size_t)NPTS * 96];
static __device__ float g_a1 [(size_t)NPTS * 256];
static __device__ float g_a2 [(size_t)NPTS * 512];
static __device__ float g_a3 [(size_t)NPTS * 768];
static __device__ float g_pf [(size_t)NPTS * 768];
static __device__ float g_scores[NPTS];
static __device__ int   g_offsets[NBATCH + 1];
static __device__ int   g_selidx[NBATCH * MAXTOK];

// ---------------- per-batch offsets via binary search (batch_ids sorted) ----------
__global__ void offsets_kernel(const int* __restrict__ bids)
{
    int b = threadIdx.x;
    if (b > NBATCH) return;
    int lo = 0, hi = NPTS;
    while (lo < hi) {
        int mid = (lo + hi) >> 1;
        if (bids[mid] < b) lo = mid + 1; else hi = mid;
    }
    g_offsets[b] = lo;
}

// ---------------- pointwise: LN + spatial MLP + concat -> g_h96 -------------------
__global__ void __launch_bounds__(128)
pointwise_kernel(const float* __restrict__ coords, const float* __restrict__ feats,
                 const float* __restrict__ times,
                 const float* __restrict__ ln_g, const float* __restrict__ ln_b,
                 const float* __restrict__ sw1, const float* __restrict__ sb1,
                 const float* __restrict__ sw2, const float* __restrict__ sb2)
{
    __shared__ float s_w1[4 * 64];
    __shared__ float s_w2[64 * 64];
    __shared__ float s_b1[64], s_b2[64], s_g[4], s_bn[4];
    for (int i = threadIdx.x; i < 256; i += blockDim.x) s_w1[i] = sw1[i];
    for (int i = threadIdx.x; i < 4096; i += blockDim.x) s_w2[i] = sw2[i];
    if (threadIdx.x < 64) { s_b1[threadIdx.x] = sb1[threadIdx.x]; s_b2[threadIdx.x] = sb2[threadIdx.x]; }
    if (threadIdx.x < 4)  { s_g[threadIdx.x] = ln_g[threadIdx.x]; s_bn[threadIdx.x] = ln_b[threadIdx.x]; }
    __syncthreads();

    int i = blockIdx.x * blockDim.x + threadIdx.x;
    if (i >= NPTS) return;

    float x[4];
    x[0] = coords[3 * i + 0];
    x[1] = coords[3 * i + 1];
    x[2] = coords[3 * i + 2];
    x[3] = times[i];
    float mu = 0.25f * (x[0] + x[1] + x[2] + x[3]);
    float var = 0.f;
#pragma unroll
    for (int j = 0; j < 4; j++) { float d = x[j] - mu; var += d * d; }
    var *= 0.25f;
    float inv = rsqrtf(var + 1e-5f);
    float xn[4];
#pragma unroll
    for (int j = 0; j < 4; j++) xn[j] = (x[j] - mu) * inv * s_g[j] + s_bn[j];

    float t1[64];
#pragma unroll 8
    for (int j = 0; j < 64; j++) {
        float a = s_b1[j];
        a += xn[0] * s_w1[j];
        a += xn[1] * s_w1[64 + j];
        a += xn[2] * s_w1[128 + j];
        a += xn[3] * s_w1[192 + j];
        t1[j] = fmaxf(a, 0.f);
    }

    float* out = &g_h96[(size_t)i * 96];
#pragma unroll 8
    for (int j = 0; j < 32; j++) out[j] = feats[32 * i + j];

    for (int j = 0; j < 64; j++) {
        float a = s_b2[j];
#pragma unroll 16
        for (int k = 0; k < 64; k++) a += t1[k] * s_w2[k * 64 + j];
        out[32 + j] = fmaxf(a, 0.f);
    }
}

// ---------------- generic fp32 GEMM, 128x128x16, double-buffered ------------------
// mode 0: C = (relu?)(A@W + bias)
// mode 1: scoresOut[row] += sum_n relu(A@W + bias)[row,n] * w2[n]   (atomic partials)
__global__ void __launch_bounds__(256)
gemm_kernel(const float* __restrict__ A, const float* __restrict__ W,
            const float* __restrict__ bias, float* __restrict__ C,
            int K, int N, int do_relu,
            const float* __restrict__ w2, float* __restrict__ scoresOut, int mode)
{
    __shared__ float As[2][16][128];
    __shared__ float Bs[2][16][128];
    const int m0 = blockIdx.y * 128;
    const int n0 = blockIdx.x * 128;
    const int tid = threadIdx.x;
    const int tx = tid & 15;
    const int ty = tid >> 4;
    const int arow = tid >> 2;
    const int acol = (tid & 3) << 2;
    const int brow = tid >> 5;
    const int bcol = (tid & 31) << 2;

    const float* ag0 = A + (size_t)(m0 + arow) * K + acol;
    const float* ag1 = ag0 + (size_t)64 * K;
    const float* wg0 = W + (size_t)brow * N + n0 + bcol;
    const float* wg1 = wg0 + (size_t)8 * N;

    float acc[8][8];
#pragma unroll
    for (int i = 0; i < 8; i++)
#pragma unroll
        for (int j = 0; j < 8; j++) acc[i][j] = 0.f;

    const int nk = K >> 4;

    // prologue: tile 0 into buffer 0
    {
        float4 va0 = *(const float4*)(ag0);
        float4 va1 = *(const float4*)(ag1);
        float4 vb0 = *(const float4*)(wg0);
        float4 vb1 = *(const float4*)(wg1);
        As[0][acol + 0][arow] = va0.x; As[0][acol + 1][arow] = va0.y;
        As[0][acol + 2][arow] = va0.z; As[0][acol + 3][arow] = va0.w;
        As[0][acol + 0][arow + 64] = va1.x; As[0][acol + 1][arow + 64] = va1.y;
        As[0][acol + 2][arow + 64] = va1.z; As[0][acol + 3][arow + 64] = va1.w;
        *(float4*)&Bs[0][brow][bcol] = vb0;
        *(float4*)&Bs[0][brow + 8][bcol] = vb1;
    }
    __syncthreads();

    for (int kt = 0; kt < nk; kt++) {
        const int buf = kt & 1;
        float4 va0, va1, vb0, vb1;
        const bool more = (kt + 1 < nk);
        if (more) {
            va0 = *(const float4*)(ag0 + (kt + 1) * 16);
            va1 = *(const float4*)(ag1 + (kt + 1) * 16);
            const float* w0 = W + (size_t)((kt + 1) * 16 + brow) * N + n0 + bcol;
            vb0 = *(const float4*)(w0);
            vb1 = *(const float4*)(w0 + (size_t)8 * N);
        }
#pragma unroll
        for (int kk = 0; kk < 16; kk++) {
            float4 a0 = *(const float4*)&As[buf][kk][ty * 8];
            float4 a1 = *(const float4*)&As[buf][kk][ty * 8 + 4];
            float4 b0 = *(const float4*)&Bs[buf][kk][tx * 8];
            float4 b1 = *(const float4*)&Bs[buf][kk][tx * 8 + 4];
            float ar[8] = {a0.x, a0.y, a0.z, a0.w, a1.x, a1.y, a1.z, a1.w};
            float br[8] = {b0.x, b0.y, b0.z, b0.w, b1.x, b1.y, b1.z, b1.w};
#pragma unroll
            for (int i = 0; i < 8; i++)
#pragma unroll
                for (int j = 0; j < 8; j++)
                    acc[i][j] = fmaf(ar[i], br[j], acc[i][j]);
        }
        if (more) {
            const int nb = buf ^ 1;
            As[nb][acol + 0][arow] = va0.x; As[nb][acol + 1][arow] = va0.y;
            As[nb][acol + 2][arow] = va0.z; As[nb][acol + 3][arow] = va0.w;
            As[nb][acol + 0][arow + 64] = va1.x; As[nb][acol + 1][arow + 64] = va1.y;
            As[nb][acol + 2][arow + 64] = va1.z; As[nb][acol + 3][arow + 64] = va1.w;
            *(float4*)&Bs[nb][brow][bcol] = vb0;
            *(float4*)&Bs[nb][brow + 8][bcol] = vb1;
        }
        __syncthreads();
    }

    if (mode == 0) {
        float bia[8];
#pragma unroll
        for (int j = 0; j < 8; j++) bia[j] = bias[n0 + tx * 8 + j];
#pragma unroll
        for (int i = 0; i < 8; i++) {
            int gr = m0 + ty * 8 + i;
            float v[8];
#pragma unroll
            for (int j = 0; j < 8; j++) {
                v[j] = acc[i][j] + bia[j];
                if (do_relu) v[j] = fmaxf(v[j], 0.f);
            }
            float4* crow = (float4*)(C + (size_t)gr * N + n0 + tx * 8);
            crow[0] = make_float4(v[0], v[1], v[2], v[3]);
            crow[1] = make_float4(v[4], v[5], v[6], v[7]);
        }
    } else {
        float bia[8], w2v[8];
#pragma unroll
        for (int j = 0; j < 8; j++) {
            bia[j] = bias[n0 + tx * 8 + j];
            w2v[j] = w2[n0 + tx * 8 + j];
        }
#pragma unroll
        for (int i = 0; i < 8; i++) {
            float s = 0.f;
#pragma unroll
            for (int j = 0; j < 8; j++) {
                float v = fmaxf(acc[i][j] + bia[j], 0.f);
                s = fmaf(v, w2v[j], s);
            }
#pragma unroll
            for (int o = 8; o >= 1; o >>= 1)
                s += __shfl_xor_sync(0xffffffffu, s, o);
            if (tx == 0) atomicAdd(&scoresOut[m0 + ty * 8 + i], s);
        }
    }
}

// ---------------- init scores to hb2 -----------------------------------------------
__global__ void init_scores_kernel(const float* __restrict__ hb2)
{
    int i = blockIdx.x * blockDim.x + threadIdx.x;
    if (i < NPTS) g_scores[i] = hb2[0];
}

// ---------------- per-batch exact top-128 (tie-break: smaller position) -----------
__global__ void __launch_bounds__(256)
select_kernel()
{
    __shared__ unsigned long long keys[MAXPB];
    __shared__ unsigned long long red[8];
    const int b = blockIdx.x;
    const int off = g_offsets[b];
    int cnt = g_offsets[b + 1] - off;
    if (cnt > MAXPB) cnt = MAXPB;

    for (int p = threadIdx.x; p < cnt; p += 256) {
        float s = g_scores[off + p];
        unsigned u = __float_as_uint(s);
        u = (u & 0x80000000u) ? ~u : (u | 0x80000000u);
        keys[p] = ((unsigned long long)u << 32) | (unsigned)(0x7FFFFFFFu - p);
    }
    __syncthreads();

    const int nsel = (cnt < MAXTOK) ? cnt : MAXTOK;
    for (int t = 0; t < nsel; t++) {
        unsigned long long best = 0ull;
        for (int p = threadIdx.x; p < cnt; p += 256) {
            unsigned long long k = keys[p];
            if (k > best) best = k;
        }
#pragma unroll
        for (int o = 16; o >= 1; o >>= 1) {
            unsigned long long other = __shfl_xor_sync(0xffffffffu, best, o);
            if (other > best) best = other;
        }
        if ((threadIdx.x & 31) == 0) red[threadIdx.x >> 5] = best;
        __syncthreads();
        if (threadIdx.x == 0) {
            unsigned long long m = red[0];
#pragma unroll
            for (int w = 1; w < 8; w++) if (red[w] > m) m = red[w];
            int pos = 0x7FFFFFFF - (int)(unsigned)(m & 0xFFFFFFFFull);
            keys[pos] = 0ull;
            g_selidx[b * MAXTOK + t] = off + pos;
        }
        __syncthreads();
    }
    if (threadIdx.x == 0)
        for (int t = nsel; t < MAXTOK; t++) g_selidx[b * MAXTOK + t] = -1;
}

// ---------------- gather tokens / centroids / mask into d_out ---------------------
__global__ void __launch_bounds__(192)
gather_kernel(const float* __restrict__ coords, const float* __restrict__ times,
              float* __restrict__ out)
{
    const int slot = blockIdx.x;                 // b*128 + t
    const int idx = g_selidx[slot];
    float4* d4 = (float4*)(out + (size_t)slot * TOKDIM);
    if (idx >= 0) {
        const float4* s4 = (const float4*)&g_pf[(size_t)idx * TOKDIM];
        for (int j = threadIdx.x; j < TOKDIM / 4; j += blockDim.x) d4[j] = s4[j];
    } else {
        float4 z = make_float4(0.f, 0.f, 0.f, 0.f);
        for (int j = threadIdx.x; j < TOKDIM / 4; j += blockDim.x) d4[j] = z;
    }
    if (threadIdx.x == 0) {
        float* cen = out + (size_t)NBATCH * MAXTOK * TOKDIM + (size_t)slot * 4;
        float* msk = out + (size_t)NBATCH * MAXTOK * TOKDIM + (size_t)NBATCH * MAXTOK * 4 + slot;
        if (idx >= 0) {
            cen[0] = coords[3 * idx + 0];
            cen[1] = coords[3 * idx + 1];
            cen[2] = coords[3 * idx + 2];
            cen[3] = times[idx];
            *msk = 1.0f;
        } else {
            cen[0] = 0.f; cen[1] = 0.f; cen[2] = 0.f; cen[3] = 0.f;
            *msk = 0.0f;
        }
    }
}

// ---------------- launch ------------------------------------------------------------
extern "C" void kernel_launch(void* const* d_in, const int* in_sizes, int n_in,
                              void* d_out, int out_size)
{
    const float* coords = (const float*)d_in[0];
    const float* feats  = (const float*)d_in[1];
    const float* times  = (const float*)d_in[2];
    const int*   bids   = (const int*)  d_in[3];
    const float* ln_g = (const float*)d_in[4];
    const float* ln_b = (const float*)d_in[5];
    const float* sw1  = (const float*)d_in[6];
    const float* sb1  = (const float*)d_in[7];
    const float* sw2  = (const float*)d_in[8];
    const float* sb2  = (const float*)d_in[9];
    const float* mw1  = (const float*)d_in[10];
    const float* mb1  = (const float*)d_in[11];
    const float* mw2  = (const float*)d_in[12];
    const float* mb2  = (const float*)d_in[13];
    const float* mw3  = (const float*)d_in[14];
    const float* mb3  = (const float*)d_in[15];
    const float* mw4  = (const float*)d_in[16];
    const float* mb4  = (const float*)d_in[17];
    const float* hw1  = (const float*)d_in[18];
    const float* hb1  = (const float*)d_in[19];
    const float* hw2  = (const float*)d_in[20];
    const float* hb2  = (const float*)d_in[21];
    float* out = (float*)d_out;

    // device-global scratch addresses (query only; no allocation)
    void *p_h96, *p_a1, *p_a2, *p_a3, *p_pf, *p_scores;
    cudaGetSymbolAddress(&p_h96, g_h96);
    cudaGetSymbolAddress(&p_a1, g_a1);
    cudaGetSymbolAddress(&p_a2, g_a2);
    cudaGetSymbolAddress(&p_a3, g_a3);
    cudaGetSymbolAddress(&p_pf, g_pf);
    cudaGetSymbolAddress(&p_scores, g_scores);
    float* h96 = (float*)p_h96;
    float* a1 = (float*)p_a1;
    float* a2 = (float*)p_a2;
    float* a3 = (float*)p_a3;
    float* pf = (float*)p_pf;
    float* scores = (float*)p_scores;

    offsets_kernel<<<1, NBATCH + 1>>>(bids);
    pointwise_kernel<<<NPTS / 128, 128>>>(coords, feats, times, ln_g, ln_b, sw1, sb1, sw2, sb2);

    // MLP chain
    gemm_kernel<<<dim3(256 / 128, NPTS / 128), 256>>>(h96, mw1, mb1, a1, 96, 256, 1, nullptr, nullptr, 0);
    gemm_kernel<<<dim3(512 / 128, NPTS / 128), 256>>>(a1, mw2, mb2, a2, 256, 512, 1, nullptr, nullptr, 0);
    gemm_kernel<<<dim3(768 / 128, NPTS / 128), 256>>>(a2, mw3, mb3, a3, 512, 768, 1, nullptr, nullptr, 0);
    gemm_kernel<<<dim3(768 / 128, NPTS / 128), 256>>>(a3, mw4, mb4, pf, 768, 768, 0, nullptr, nullptr, 0);

    // fused score head: relu(pf@hw1+hb1)@hw2 + hb2
    init_scores_kernel<<<NPTS / 256, 256>>>(hb2);
    gemm_kernel<<<dim3(384 / 128, NPTS / 128), 256>>>(pf, hw1, hb1, nullptr, 768, 384, 1, hw2, scores, 1);

    // per-batch top-128 + gather
    select_kernel<<<NBATCH, 256>>>();
    gather_kernel<<<NBATCH * MAXTOK, 192>>>(coords, times, out);
}

// round 8
// speedup vs baseline: 3.5683x; 3.5669x over previous
#include <cuda_runtime.h>
#include <cuda_bf16.h>
#include <cstdint>

#define NPTS   131072
#define NBATCH 64
#define MAXPB  2560
#define MAXTOK 128
#define TOKDIM 768
#define NCAND  192                 // margin: 1.5x MAXTOK
#define MC     (NBATCH * NCAND)    // 12288 = 96 * 128

typedef __nv_bfloat16 bf16;
typedef __nv_bfloat162 bf16x2;

// ------------------------------ scratch ------------------------------------
// stage 1: bf16 activations (h96 padded K=96->128)
static __device__ bf16 g_hb [(size_t)NPTS * 128];
static __device__ bf16 g_b1 [(size_t)NPTS * 256];
static __device__ bf16 g_b2 [(size_t)NPTS * 512];
static __device__ bf16 g_b3 [(size_t)NPTS * 768];
static __device__ bf16 g_bpf[(size_t)NPTS * 768];
static __device__ float g_h96f[(size_t)NPTS * 96];    // fp32 h96 for stage 2
static __device__ float g_scores[NPTS];               // approx scores
// stage-1 weights: [N, Kpad] bf16
static __device__ bf16 g_w1b[256 * 128];
static __device__ bf16 g_w2b[512 * 256];
static __device__ bf16 g_w3b[768 * 512];
static __device__ bf16 g_w4b[768 * 768];
static __device__ bf16 g_hwb[384 * 768];
// stage 2: compact fp32 chain
static __device__ float g_Xc [(size_t)MC * 96];
static __device__ float g_c1 [(size_t)MC * 256];
static __device__ float g_c2 [(size_t)MC * 512];
static __device__ float g_c3 [(size_t)MC * 768];
static __device__ float g_pfc[(size_t)MC * 768];
static __device__ float g_scoresc[MC];
// selection state
static __device__ int g_offsets[NBATCH + 1];
static __device__ int g_cand[MC];                     // global idx or -1
static __device__ int g_selidx[NBATCH * MAXTOK];      // global idx or -1
static __device__ int g_selcomp[NBATCH * MAXTOK];     // compact idx or -1

// ------------------------------ PTX helpers --------------------------------
__device__ __forceinline__ uint32_t smem_u32(const void* p) {
    uint32_t a;
    asm("{ .reg .u64 t; cvta.to.shared.u64 t, %1; cvt.u32.u64 %0, t; }" : "=r"(a) : "l"(p));
    return a;
}
__device__ __forceinline__ void cp16(uint32_t dst, const void* src) {
    asm volatile("cp.async.cg.shared.global [%0], [%1], 16;" :: "r"(dst), "l"(src));
}
#define CP_COMMIT() asm volatile("cp.async.commit_group;" ::: "memory")
#define CP_WAIT0()  asm volatile("cp.async.wait_group 0;" ::: "memory")
#define CP_WAIT1()  asm volatile("cp.async.wait_group 1;" ::: "memory")

__device__ __forceinline__ void ldsm4(uint32_t& r0, uint32_t& r1, uint32_t& r2, uint32_t& r3,
                                      uint32_t a) {
    asm volatile("ldmatrix.sync.aligned.m8n8.x4.shared.b16 {%0,%1,%2,%3}, [%4];"
                 : "=r"(r0), "=r"(r1), "=r"(r2), "=r"(r3) : "r"(a));
}
__device__ __forceinline__ void ldsm2(uint32_t& r0, uint32_t& r1, uint32_t a) {
    asm volatile("ldmatrix.sync.aligned.m8n8.x2.shared.b16 {%0,%1}, [%2];"
                 : "=r"(r0), "=r"(r1) : "r"(a));
}
__device__ __forceinline__ void mma_bf16(float* c, const uint32_t* a, const uint32_t* b) {
    asm volatile("mma.sync.aligned.m16n8k16.row.col.f32.bf16.bf16.f32 "
                 "{%0,%1,%2,%3}, {%4,%5,%6,%7}, {%8,%9}, {%0,%1,%2,%3};"
                 : "+f"(c[0]), "+f"(c[1]), "+f"(c[2]), "+f"(c[3])
                 : "r"(a[0]), "r"(a[1]), "r"(a[2]), "r"(a[3]), "r"(b[0]), "r"(b[1]));
}

// ------------------------------ offsets ------------------------------------
__global__ void offsets_kernel(const int* __restrict__ bids)
{
    int b = threadIdx.x;
    if (b > NBATCH) return;
    int lo = 0, hi = NPTS;
    while (lo < hi) {
        int mid = (lo + hi) >> 1;
        if (bids[mid] < b) lo = mid + 1; else hi = mid;
    }
    g_offsets[b] = lo;
}

// ---- weight transpose to bf16: [Kreal,N] fp32 -> [N,Kpad] bf16 -------------
__global__ void prep_wb(const float* __restrict__ W, bf16* __restrict__ T,
                        int Kreal, int Kpad, int N)
{
    int i = blockIdx.x * 256 + threadIdx.x;
    if (i >= N * Kpad) return;
    int n = i / Kpad, k = i - n * Kpad;
    float v = (k < Kreal) ? W[(size_t)k * N + n] : 0.f;
    T[i] = __float2bfloat16(v);
}

// ---------------- pointwise: LN + spatial MLP + concat ----------------------
__global__ void __launch_bounds__(128)
pointwise_kernel(const float* __restrict__ coords, const float* __restrict__ feats,
                 const float* __restrict__ times,
                 const float* __restrict__ ln_g, const float* __restrict__ ln_b,
                 const float* __restrict__ sw1, const float* __restrict__ sb1,
                 const float* __restrict__ sw2, const float* __restrict__ sb2)
{
    __shared__ float s_w1[4 * 64];
    __shared__ float s_w2[64 * 64];
    __shared__ float s_b1[64], s_b2[64], s_g[4], s_bn[4];
    for (int i = threadIdx.x; i < 256; i += blockDim.x) s_w1[i] = sw1[i];
    for (int i = threadIdx.x; i < 4096; i += blockDim.x) s_w2[i] = sw2[i];
    if (threadIdx.x < 64) { s_b1[threadIdx.x] = sb1[threadIdx.x]; s_b2[threadIdx.x] = sb2[threadIdx.x]; }
    if (threadIdx.x < 4)  { s_g[threadIdx.x] = ln_g[threadIdx.x]; s_bn[threadIdx.x] = ln_b[threadIdx.x]; }
    __syncthreads();

    int i = blockIdx.x * blockDim.x + threadIdx.x;
    if (i >= NPTS) return;

    float x[4];
    x[0] = coords[3 * i + 0];
    x[1] = coords[3 * i + 1];
    x[2] = coords[3 * i + 2];
    x[3] = times[i];
    float mu = 0.25f * (x[0] + x[1] + x[2] + x[3]);
    float var = 0.f;
#pragma unroll
    for (int j = 0; j < 4; j++) { float d = x[j] - mu; var += d * d; }
    var *= 0.25f;
    float inv = rsqrtf(var + 1e-5f);
    float xn[4];
#pragma unroll
    for (int j = 0; j < 4; j++) xn[j] = (x[j] - mu) * inv * s_g[j] + s_bn[j];

    float t1[64];
#pragma unroll 8
    for (int j = 0; j < 64; j++) {
        float a = s_b1[j];
        a += xn[0] * s_w1[j];
        a += xn[1] * s_w1[64 + j];
        a += xn[2] * s_w1[128 + j];
        a += xn[3] * s_w1[192 + j];
        t1[j] = fmaxf(a, 0.f);
    }

    bf16* ob = &g_hb[(size_t)i * 128];
    float* of = &g_h96f[(size_t)i * 96];
#pragma unroll 8
    for (int j = 0; j < 32; j++) {
        float v = feats[32 * i + j];
        ob[j] = __float2bfloat16(v);
        of[j] = v;
    }
    for (int j = 0; j < 64; j++) {
        float a = s_b2[j];
#pragma unroll 16
        for (int k = 0; k < 64; k++) a += t1[k] * s_w2[k * 64 + j];
        a = fmaxf(a, 0.f);
        ob[32 + j] = __float2bfloat16(a);
        of[32 + j] = a;
    }
    bf16 z = __float2bfloat16(0.f);
#pragma unroll 8
    for (int j = 96; j < 128; j++) ob[j] = z;
}

// -------- stage-1 bf16 mma.sync GEMM: 128x128 CTA tile, K-chunk 64 ----------
// mode 0: out = bf16( (relu?)(X@W^T + bias) )
// mode 1: scores[row] += sum_n relu(X@W^T + bias)[row,n] * w2[n]
#define ROWB        144
#define MAT_BYTES   (128 * ROWB)
#define STAGE_BYTES (2 * MAT_BYTES)
#define GEMM_SMEM   (2 * STAGE_BYTES)

__global__ void __launch_bounds__(256)
mma_gemm_b(const bf16* __restrict__ X, const bf16* __restrict__ W,
           const float* __restrict__ bias, int K, int N, int do_relu,
           bf16* __restrict__ outB,
           const float* __restrict__ w2, float* __restrict__ scores, int mode)
{
    extern __shared__ char smem[];
    const uint32_t sbase = smem_u32(smem);
    const int tid = threadIdx.x;
    const int l = tid & 31, w = tid >> 5;
    const int wm = w & 1, wn = w >> 1;          // warp grid 2(m) x 4(n)
    const int m0 = blockIdx.y * 128;
    const int n0 = blockIdx.x * 128;

    float c[4][4][4];
#pragma unroll
    for (int a = 0; a < 4; a++)
#pragma unroll
        for (int b = 0; b < 4; b++)
#pragma unroll
            for (int d = 0; d < 4; d++) c[a][b][d] = 0.f;

    const int nk = K >> 6;

#define LOAD_CHUNK_B(KT, S) do {                                                 \
    const uint32_t _sb = sbase + (S) * STAGE_BYTES;                              \
    const int _kb = (KT) * 64;                                                   \
    _Pragma("unroll")                                                            \
    for (int mat = 0; mat < 2; mat++) {                                          \
        const bf16* _sp = (mat == 0) ? X : W;                                    \
        const int _rb = (mat == 0) ? m0 : n0;                                    \
        _Pragma("unroll")                                                        \
        for (int u = 0; u < 4; u++) {                                            \
            int id2 = tid + u * 256;                                             \
            int r = id2 >> 3, g = id2 & 7;                                       \
            cp16(_sb + mat * MAT_BYTES + r * ROWB + g * 16,                      \
                 _sp + (size_t)(_rb + r) * K + _kb + g * 8);                     \
        }                                                                        \
    }                                                                            \
} while (0)

    LOAD_CHUNK_B(0, 0);
    CP_COMMIT();

    for (int kt = 0; kt < nk; kt++) {
        const bool more = (kt + 1 < nk);
        if (more) { LOAD_CHUNK_B(kt + 1, (kt + 1) & 1); CP_COMMIT(); }
        if (more) CP_WAIT1(); else CP_WAIT0();
        __syncthreads();

        const uint32_t st = sbase + (kt & 1) * STAGE_BYTES;
        const uint32_t AB = st;
        const uint32_t BB = st + MAT_BYTES;

        const int ar = l & 15, ag2 = l >> 4;
        const int br = l & 7,  bg2 = (l >> 3) & 1;

#pragma unroll
        for (int ks = 0; ks < 4; ks++) {
            uint32_t ah[4][4], bh[4][2];
            const int gA = ks * 2 + ag2;
            const int gB = ks * 2 + bg2;
#pragma unroll
            for (int mt = 0; mt < 4; mt++) {
                uint32_t off = (uint32_t)(wm * 64 + mt * 16 + ar) * ROWB + gA * 16;
                ldsm4(ah[mt][0], ah[mt][1], ah[mt][2], ah[mt][3], AB + off);
            }
#pragma unroll
            for (int nt = 0; nt < 4; nt++) {
                uint32_t off = (uint32_t)(wn * 32 + nt * 8 + br) * ROWB + gB * 16;
                ldsm2(bh[nt][0], bh[nt][1], BB + off);
            }
#pragma unroll
            for (int mt = 0; mt < 4; mt++)
#pragma unroll
                for (int nt = 0; nt < 4; nt++)
                    mma_bf16(c[mt][nt], ah[mt], bh[nt]);
        }
        __syncthreads();
    }

    if (mode == 0) {
#pragma unroll
        for (int mt = 0; mt < 4; mt++) {
            const int r0 = m0 + wm * 64 + mt * 16 + (l >> 2);
            const int r1 = r0 + 8;
#pragma unroll
            for (int nt = 0; nt < 4; nt++) {
                const int cc = n0 + wn * 32 + nt * 8 + 2 * (l & 3);
                float2 bi = *(const float2*)&bias[cc];
                float v0 = c[mt][nt][0] + bi.x, v1 = c[mt][nt][1] + bi.y;
                float v2 = c[mt][nt][2] + bi.x, v3 = c[mt][nt][3] + bi.y;
                if (do_relu) {
                    v0 = fmaxf(v0, 0.f); v1 = fmaxf(v1, 0.f);
                    v2 = fmaxf(v2, 0.f); v3 = fmaxf(v3, 0.f);
                }
                bf16x2 p01; p01.x = __float2bfloat16(v0); p01.y = __float2bfloat16(v1);
                bf16x2 p23; p23.x = __float2bfloat16(v2); p23.y = __float2bfloat16(v3);
                *(bf16x2*)&outB[(size_t)r0 * N + cc] = p01;
                *(bf16x2*)&outB[(size_t)r1 * N + cc] = p23;
            }
        }
    } else {
#pragma unroll
        for (int mt = 0; mt < 4; mt++) {
            float s0 = 0.f, s1 = 0.f;
#pragma unroll
            for (int nt = 0; nt < 4; nt++) {
                const int cc = n0 + wn * 32 + nt * 8 + 2 * (l & 3);
                float2 bi = *(const float2*)&bias[cc];
                float2 wv = *(const float2*)&w2[cc];
                s0 += fmaxf(c[mt][nt][0] + bi.x, 0.f) * wv.x
                    + fmaxf(c[mt][nt][1] + bi.y, 0.f) * wv.y;
                s1 += fmaxf(c[mt][nt][2] + bi.x, 0.f) * wv.x
                    + fmaxf(c[mt][nt][3] + bi.y, 0.f) * wv.y;
            }
            s0 += __shfl_xor_sync(0xffffffffu, s0, 1);
            s0 += __shfl_xor_sync(0xffffffffu, s0, 2);
            s1 += __shfl_xor_sync(0xffffffffu, s1, 1);
            s1 += __shfl_xor_sync(0xffffffffu, s1, 2);
            if ((l & 3) == 0) {
                const int r0 = m0 + wm * 64 + mt * 16 + (l >> 2);
                atomicAdd(&scores[r0], s0);
                atomicAdd(&scores[r0 + 8], s1);
            }
        }
    }
}

// -------- stage-2 fp32 SIMT GEMM (proven round-2 kernel) --------------------
__global__ void __launch_bounds__(256)
gemm_kernel(const float* __restrict__ A, const float* __restrict__ W,
            const float* __restrict__ bias, float* __restrict__ C,
            int K, int N, int do_relu,
            const float* __restrict__ w2, float* __restrict__ scoresOut, int mode)
{
    __shared__ float As[2][16][128];
    __shared__ float Bs[2][16][128];
    const int m0 = blockIdx.y * 128;
    const int n0 = blockIdx.x * 128;
    const int tid = threadIdx.x;
    const int tx = tid & 15;
    const int ty = tid >> 4;
    const int arow = tid >> 2;
    const int acol = (tid & 3) << 2;
    const int brow = tid >> 5;
    const int bcol = (tid & 31) << 2;

    const float* ag0 = A + (size_t)(m0 + arow) * K + acol;
    const float* ag1 = ag0 + (size_t)64 * K;
    const float* wg0 = W + (size_t)brow * N + n0 + bcol;
    const float* wg1 = wg0 + (size_t)8 * N;

    float acc[8][8];
#pragma unroll
    for (int i = 0; i < 8; i++)
#pragma unroll
        for (int j = 0; j < 8; j++) acc[i][j] = 0.f;

    const int nk = K >> 4;
    {
        float4 va0 = *(const float4*)(ag0);
        float4 va1 = *(const float4*)(ag1);
        float4 vb0 = *(const float4*)(wg0);
        float4 vb1 = *(const float4*)(wg1);
        As[0][acol + 0][arow] = va0.x; As[0][acol + 1][arow] = va0.y;
        As[0][acol + 2][arow] = va0.z; As[0][acol + 3][arow] = va0.w;
        As[0][acol + 0][arow + 64] = va1.x; As[0][acol + 1][arow + 64] = va1.y;
        As[0][acol + 2][arow + 64] = va1.z; As[0][acol + 3][arow + 64] = va1.w;
        *(float4*)&Bs[0][brow][bcol] = vb0;
        *(float4*)&Bs[0][brow + 8][bcol] = vb1;
    }
    __syncthreads();

    for (int kt = 0; kt < nk; kt++) {
        const int buf = kt & 1;
        float4 va0, va1, vb0, vb1;
        const bool more = (kt + 1 < nk);
        if (more) {
            va0 = *(const float4*)(ag0 + (kt + 1) * 16);
            va1 = *(const float4*)(ag1 + (kt + 1) * 16);
            const float* w0 = W + (size_t)((kt + 1) * 16 + brow) * N + n0 + bcol;
            vb0 = *(const float4*)(w0);
            vb1 = *(const float4*)(w0 + (size_t)8 * N);
        }
#pragma unroll
        for (int kk = 0; kk < 16; kk++) {
            float4 a0 = *(const float4*)&As[buf][kk][ty * 8];
            float4 a1 = *(const float4*)&As[buf][kk][ty * 8 + 4];
            float4 b0 = *(const float4*)&Bs[buf][kk][tx * 8];
            float4 b1 = *(const float4*)&Bs[buf][kk][tx * 8 + 4];
            float ar[8] = {a0.x, a0.y, a0.z, a0.w, a1.x, a1.y, a1.z, a1.w};
            float br[8] = {b0.x, b0.y, b0.z, b0.w, b1.x, b1.y, b1.z, b1.w};
#pragma unroll
            for (int i = 0; i < 8; i++)
#pragma unroll
                for (int j = 0; j < 8; j++)
                    acc[i][j] = fmaf(ar[i], br[j], acc[i][j]);
        }
        if (more) {
            const int nb = buf ^ 1;
            As[nb][acol + 0][arow] = va0.x; As[nb][acol + 1][arow] = va0.y;
            As[nb][acol + 2][arow] = va0.z; As[nb][acol + 3][arow] = va0.w;
            As[nb][acol + 0][arow + 64] = va1.x; As[nb][acol + 1][arow + 64] = va1.y;
            As[nb][acol + 2][arow + 64] = va1.z; As[nb][acol + 3][arow + 64] = va1.w;
            *(float4*)&Bs[nb][brow][bcol] = vb0;
            *(float4*)&Bs[nb][brow + 8][bcol] = vb1;
        }
        __syncthreads();
    }

    if (mode == 0) {
        float bia[8];
#pragma unroll
        for (int j = 0; j < 8; j++) bia[j] = bias[n0 + tx * 8 + j];
#pragma unroll
        for (int i = 0; i < 8; i++) {
            int gr = m0 + ty * 8 + i;
            float v[8];
#pragma unroll
            for (int j = 0; j < 8; j++) {
                v[j] = acc[i][j] + bia[j];
                if (do_relu) v[j] = fmaxf(v[j], 0.f);
            }
            float4* crow = (float4*)(C + (size_t)gr * N + n0 + tx * 8);
            crow[0] = make_float4(v[0], v[1], v[2], v[3]);
            crow[1] = make_float4(v[4], v[5], v[6], v[7]);
        }
    } else {
        float bia[8], w2v[8];
#pragma unroll
        for (int j = 0; j < 8; j++) {
            bia[j] = bias[n0 + tx * 8 + j];
            w2v[j] = w2[n0 + tx * 8 + j];
        }
#pragma unroll
        for (int i = 0; i < 8; i++) {
            float s = 0.f;
#pragma unroll
            for (int j = 0; j < 8; j++) {
                float v = fmaxf(acc[i][j] + bia[j], 0.f);
                s = fmaf(v, w2v[j], s);
            }
#pragma unroll
            for (int o = 8; o >= 1; o >>= 1)
                s += __shfl_xor_sync(0xffffffffu, s, o);
            if (tx == 0) atomicAdd(&scoresOut[m0 + ty * 8 + i], s);
        }
    }
}

// ---------------- init scores ------------------------------------------------
__global__ void init_scores_kernel(float* __restrict__ s, int n, const float* __restrict__ hb2)
{
    int i = blockIdx.x * blockDim.x + threadIdx.x;
    if (i < n) s[i] = hb2[0];
}

// ---------------- stage-1 select: per-batch top-NCAND by approx score --------
__global__ void __launch_bounds__(256)
select1_kernel()
{
    __shared__ unsigned long long keys[MAXPB];
    __shared__ unsigned long long red[8];
    const int b = blockIdx.x;
    const int off = g_offsets[b];
    int cnt = g_offsets[b + 1] - off;
    if (cnt > MAXPB) cnt = MAXPB;

    for (int p = threadIdx.x; p < cnt; p += 256) {
        float s = g_scores[off + p];
        unsigned u = __float_as_uint(s);
        u = (u & 0x80000000u) ? ~u : (u | 0x80000000u);
        keys[p] = ((unsigned long long)u << 32) | (unsigned)(0x7FFFFFFFu - p);
    }
    __syncthreads();

    const int nsel = (cnt < NCAND) ? cnt : NCAND;
    for (int t = 0; t < nsel; t++) {
        unsigned long long best = 0ull;
        for (int p = threadIdx.x; p < cnt; p += 256) {
            unsigned long long k = keys[p];
            if (k > best) best = k;
        }
#pragma unroll
        for (int o = 16; o >= 1; o >>= 1) {
            unsigned long long other = __shfl_xor_sync(0xffffffffu, best, o);
            if (other > best) best = other;
        }
        if ((threadIdx.x & 31) == 0) red[threadIdx.x >> 5] = best;
        __syncthreads();
        if (threadIdx.x == 0) {
            unsigned long long m = red[0];
#pragma unroll
            for (int w = 1; w < 8; w++) if (red[w] > m) m = red[w];
            int pos = 0x7FFFFFFF - (int)(unsigned)(m & 0xFFFFFFFFull);
            keys[pos] = 0ull;
            g_cand[b * NCAND + t] = off + pos;
        }
        __syncthreads();
    }
    if (threadIdx.x == 0)
        for (int t = nsel; t < NCAND; t++) g_cand[b * NCAND + t] = -1;
}

// ---------------- compact candidate h96 rows ---------------------------------
__global__ void compact_kernel()
{
    int i = blockIdx.x * blockDim.x + threadIdx.x;   // MC * 96 elements
    if (i >= MC * 96) return;
    int c = i / 96, j = i - c * 96;
    int cand = g_cand[c];
    g_Xc[i] = (cand >= 0) ? g_h96f[(size_t)cand * 96 + j] : 0.f;
}

// ---------------- stage-2 select: exact top-128 among candidates -------------
__global__ void __launch_bounds__(256)
select2_kernel()
{
    __shared__ unsigned long long keys[NCAND];
    __shared__ unsigned long long red[8];
    const int b = blockIdx.x;
    const int off = g_offsets[b];
    int cnt = g_offsets[b + 1] - off;
    if (cnt > MAXPB) cnt = MAXPB;

    for (int t = threadIdx.x; t < NCAND; t += 256) {
        int c = b * NCAND + t;
        int cand = g_cand[c];
        unsigned long long k = 0ull;
        if (cand >= 0) {
            float s = g_scoresc[c];
            unsigned u = __float_as_uint(s);
            u = (u & 0x80000000u) ? ~u : (u | 0x80000000u);
            // tie-break: smaller position-in-batch (== smaller global idx) wins
            k = ((unsigned long long)u << 32) | (unsigned)(0x7FFFFFFFu - cand);
        }
        keys[t] = k;
    }
    __syncthreads();

    const int nsel = (cnt < MAXTOK) ? cnt : MAXTOK;
    for (int t = 0; t < nsel; t++) {
        unsigned long long best = 0ull;
        int bestpos = -1;
        for (int p = threadIdx.x; p < NCAND; p += 256) {
            unsigned long long k = keys[p];
            if (k > best) { best = k; bestpos = p; }
        }
#pragma unroll
        for (int o = 16; o >= 1; o >>= 1) {
            unsigned long long ok = __shfl_xor_sync(0xffffffffu, best, o);
            int op = __shfl_xor_sync(0xffffffffu, bestpos, o);
            if (ok > best) { best = ok; bestpos = op; }
        }
        if ((threadIdx.x & 31) == 0)
            red[threadIdx.x >> 5] = ((unsigned long long)(unsigned)bestpos << 48) ^ 0ull,
            red[threadIdx.x >> 5] = best;   // store key; pos recovered below
        __syncthreads();
        // recover argmax across warps via shared scan by thread 0
        if (threadIdx.x == 0) {
            unsigned long long m = 0ull;
#pragma unroll
            for (int w = 0; w < 8; w++) if (red[w] > m) m = red[w];
            // find position of m
            int pos = -1;
            for (int p = 0; p < NCAND; p++)
                if (keys[p] == m) { pos = p; break; }
            keys[pos] = 0ull;
            int c = b * NCAND + pos;
            g_selidx[b * MAXTOK + t] = g_cand[c];
            g_selcomp[b * MAXTOK + t] = c;
        }
        __syncthreads();
    }
    if (threadIdx.x == 0)
        for (int t = nsel; t < MAXTOK; t++) {
            g_selidx[b * MAXTOK + t] = -1;
            g_selcomp[b * MAXTOK + t] = -1;
        }
}

// ---------------- gather (exact pf rows from compact chain) ------------------
__global__ void __launch_bounds__(192)
gather_kernel(const float* __restrict__ coords, const float* __restrict__ times,
              float* __restrict__ out)
{
    const int slot = blockIdx.x;
    const int idx = g_selidx[slot];
    const int comp = g_selcomp[slot];
    float4* d4 = (float4*)(out + (size_t)slot * TOKDIM);
    if (idx >= 0) {
        const float4* s4 = (const float4*)&g_pfc[(size_t)comp * TOKDIM];
        for (int j = threadIdx.x; j < TOKDIM / 4; j += blockDim.x) d4[j] = s4[j];
    } else {
        float4 z = make_float4(0.f, 0.f, 0.f, 0.f);
        for (int j = threadIdx.x; j < TOKDIM / 4; j += blockDim.x) d4[j] = z;
    }
    if (threadIdx.x == 0) {
        float* cen = out + (size_t)NBATCH * MAXTOK * TOKDIM + (size_t)slot * 4;
        float* msk = out + (size_t)NBATCH * MAXTOK * TOKDIM + (size_t)NBATCH * MAXTOK * 4 + slot;
        if (idx >= 0) {
            cen[0] = coords[3 * idx + 0];
            cen[1] = coords[3 * idx + 1];
            cen[2] = coords[3 * idx + 2];
            cen[3] = times[idx];
            *msk = 1.0f;
        } else {
            cen[0] = 0.f; cen[1] = 0.f; cen[2] = 0.f; cen[3] = 0.f;
            *msk = 0.0f;
        }
    }
}

// ---------------- launch ------------------------------------------------------
extern "C" void kernel_launch(void* const* d_in, const int* in_sizes, int n_in,
                              void* d_out, int out_size)
{
    const float* coords = (const float*)d_in[0];
    const float* feats  = (const float*)d_in[1];
    const float* times  = (const float*)d_in[2];
    const int*   bids   = (const int*)  d_in[3];
    const float* ln_g = (const float*)d_in[4];
    const float* ln_b = (const float*)d_in[5];
    const float* sw1  = (const float*)d_in[6];
    const float* sb1  = (const float*)d_in[7];
    const float* sw2  = (const float*)d_in[8];
    const float* sb2  = (const float*)d_in[9];
    const float* mw1  = (const float*)d_in[10];
    const float* mb1  = (const float*)d_in[11];
    const float* mw2  = (const float*)d_in[12];
    const float* mb2  = (const float*)d_in[13];
    const float* mw3  = (const float*)d_in[14];
    const float* mb3  = (const float*)d_in[15];
    const float* mw4  = (const float*)d_in[16];
    const float* mb4  = (const float*)d_in[17];
    const float* hw1  = (const float*)d_in[18];
    const float* hb1  = (const float*)d_in[19];
    const float* hw2  = (const float*)d_in[20];
    const float* hb2  = (const float*)d_in[21];
    float* out = (float*)d_out;

    cudaFuncSetAttribute(mma_gemm_b, cudaFuncAttributeMaxDynamicSharedMemorySize, GEMM_SMEM);

    void* p;
    bf16 *hb, *b1, *b2, *b3, *bpf, *w1b, *w2b, *w3b, *w4b, *hwb;
    float *h96f, *scores, *Xc, *c1, *c2, *c3, *pfc, *scoresc;
    cudaGetSymbolAddress(&p, g_hb);   hb  = (bf16*)p;
    cudaGetSymbolAddress(&p, g_b1);   b1  = (bf16*)p;
    cudaGetSymbolAddress(&p, g_b2);   b2  = (bf16*)p;
    cudaGetSymbolAddress(&p, g_b3);   b3  = (bf16*)p;
    cudaGetSymbolAddress(&p, g_bpf);  bpf = (bf16*)p;
    cudaGetSymbolAddress(&p, g_w1b);  w1b = (bf16*)p;
    cudaGetSymbolAddress(&p, g_w2b);  w2b = (bf16*)p;
    cudaGetSymbolAddress(&p, g_w3b);  w3b = (bf16*)p;
    cudaGetSymbolAddress(&p, g_w4b);  w4b = (bf16*)p;
    cudaGetSymbolAddress(&p, g_hwb);  hwb = (bf16*)p;
    cudaGetSymbolAddress(&p, g_h96f); h96f = (float*)p;
    cudaGetSymbolAddress(&p, g_scores); scores = (float*)p;
    cudaGetSymbolAddress(&p, g_Xc);   Xc = (float*)p;
    cudaGetSymbolAddress(&p, g_c1);   c1 = (float*)p;
    cudaGetSymbolAddress(&p, g_c2);   c2 = (float*)p;
    cudaGetSymbolAddress(&p, g_c3);   c3 = (float*)p;
    cudaGetSymbolAddress(&p, g_pfc);  pfc = (float*)p;
    cudaGetSymbolAddress(&p, g_scoresc); scoresc = (float*)p;
    (void)h96f;

    offsets_kernel<<<1, NBATCH + 1>>>(bids);

    prep_wb<<<(256 * 128 + 255) / 256, 256>>>(mw1, w1b, 96, 128, 256);
    prep_wb<<<(512 * 256 + 255) / 256, 256>>>(mw2, w2b, 256, 256, 512);
    prep_wb<<<(768 * 512 + 255) / 256, 256>>>(mw3, w3b, 512, 512, 768);
    prep_wb<<<(768 * 768 + 255) / 256, 256>>>(mw4, w4b, 768, 768, 768);
    prep_wb<<<(384 * 768 + 255) / 256, 256>>>(hw1, hwb, 768, 768, 384);

    pointwise_kernel<<<NPTS / 128, 128>>>(coords, feats, times, ln_g, ln_b, sw1, sb1, sw2, sb2);
    init_scores_kernel<<<(NPTS + 255) / 256, 256>>>(scores, NPTS, hb2);

    // stage 1: approximate bf16 chain
    mma_gemm_b<<<dim3(2, NPTS / 128), 256, GEMM_SMEM>>>(hb, w1b, mb1, 128, 256, 1,
                                                        b1, nullptr, nullptr, 0);
    mma_gemm_b<<<dim3(4, NPTS / 128), 256, GEMM_SMEM>>>(b1, w2b, mb2, 256, 512, 1,
                                                        b2, nullptr, nullptr, 0);
    mma_gemm_b<<<dim3(6, NPTS / 128), 256, GEMM_SMEM>>>(b2, w3b, mb3, 512, 768, 1,
                                                        b3, nullptr, nullptr, 0);
    mma_gemm_b<<<dim3(6, NPTS / 128), 256, GEMM_SMEM>>>(b3, w4b, mb4, 768, 768, 0,
                                                        bpf, nullptr, nullptr, 0);
    mma_gemm_b<<<dim3(3, NPTS / 128), 256, GEMM_SMEM>>>(bpf, hwb, hb1, 768, 384, 1,
                                                        nullptr, hw2, scores, 1);

    // margin selection + compaction
    select1_kernel<<<NBATCH, 256>>>();
    compact_kernel<<<(MC * 96 + 255) / 256, 256>>>();
    init_scores_kernel<<<(MC + 255) / 256, 256>>>(scoresc, MC, hb2);

    // stage 2: exact fp32 chain on 12288 candidates (original fp32 weights)
    gemm_kernel<<<dim3(2, MC / 128), 256>>>(Xc, mw1, mb1, c1, 96, 256, 1, nullptr, nullptr, 0);
    gemm_kernel<<<dim3(4, MC / 128), 256>>>(c1, mw2, mb2, c2, 256, 512, 1, nullptr, nullptr, 0);
    gemm_kernel<<<dim3(6, MC / 128), 256>>>(c2, mw3, mb3, c3, 512, 768, 1, nullptr, nullptr, 0);
    gemm_kernel<<<dim3(6, MC / 128), 256>>>(c3, mw4, mb4, pfc, 768, 768, 0, nullptr, nullptr, 0);
    gemm_kernel<<<dim3(3, MC / 128), 256>>>(pfc, hw1, hb1, nullptr, 768, 384, 1, hw2, scoresc, 1);

    // exact top-128 + gather
    select2_kernel<<<NBATCH, 256>>>();
    gather_kernel<<<NBATCH * MAXTOK, 192>>>(coords, times, out);
}